// round 10
// baseline (speedup 1.0000x reference)
#include <cuda_runtime.h>
#include <cstdint>

// Permutation: x[B=16, C=64, H=256, W=256] fp32
//   out[b][i][j][k][cc][hh][ww] = x[b][i*32+cc][j*16+hh][k*16+ww]
//
// Round 10: output-contiguous tiles + async bulk store (R9 fixed).
// CTA = (b,i,j,k,chalf): covers cc = chalf*16 .. chalf*16+15, whose output is
// ONE contiguous 16 KB run (cc at output bits 6..10).
//   - threads gather input in output order (64B-granular LDG, MLP=4,
//     unroll stride bumps cc by 4 -> constant +2^16 f4 adds)
//   - STS warp-linear into contiguous smem (conflict-free)
//   - one cp.async.bulk.global.shared::cta emits the 16 KB write burst
// chalf in the lowest grid bit: adjacent CTAs emit the two halves of each
// 32 KB output run; k next for read line-pairing across CTAs.

static constexpr unsigned NBLOCKS = 16u * 2u * 16u * 16u * 2u;  // 32768

__global__ __launch_bounds__(256)
void reshape_78271484002964_kernel(const float4* __restrict__ in,
                                   float4* __restrict__ out) {
    __shared__ alignas(128) float4 sm[1024];  // 16 KB, output-linear

    unsigned bid   = blockIdx.x;
    unsigned chalf = bid & 1u;
    unsigned k     = (bid >> 1) & 15u;
    unsigned j     = (bid >> 5) & 15u;
    unsigned i     = (bid >> 9) & 1u;
    unsigned b     = bid >> 10;

    unsigned t = threadIdx.x;

    // Tile-local output f4 offset p = t + it*256: ww4=p&3, hh=(p>>2)&15,
    // cc = chalf*16 + (p>>6).
    unsigned ww4 = t & 3u;
    unsigned hh  = (t >> 2) & 15u;
    unsigned cc0 = (chalf << 4) + (t >> 6);   // cc for it=0 (base 0..3 + chalf*16)

    // input f4 addr = channel<<14 | (j*16+hh)<<6 | k<<2 | ww4
    unsigned channel = (b << 6) + (i << 5) + cc0;
    unsigned s = (channel << 14) + (((j << 4) + hh) << 6) + (k << 2) + ww4;

    // unroll stride 256 f4 => cc += 4 => +4<<14 = +65536 f4 (constant)
    float4 v0 = __ldcs(&in[s]);
    float4 v1 = __ldcs(&in[s + (1u << 16)]);
    float4 v2 = __ldcs(&in[s + (2u << 16)]);
    float4 v3 = __ldcs(&in[s + (3u << 16)]);

    sm[t        ] = v0;
    sm[t + 256u ] = v1;
    sm[t + 512u ] = v2;
    sm[t + 768u ] = v3;

    __syncthreads();

    if (t == 0) {
        // out tile base (f4): chalf<<10 | k<<11 | j<<15 | i<<19 | b<<20
        float4* dst = out + ((chalf << 10) + (k << 11) + (j << 15) +
                             (i << 19) + (b << 20));
        uint32_t src_smem = (uint32_t)__cvta_generic_to_shared(sm);

        asm volatile("fence.proxy.async.shared::cta;" ::: "memory");
        asm volatile(
            "cp.async.bulk.global.shared::cta.bulk_group [%0], [%1], %2;"
            :: "l"(dst), "r"(src_smem), "r"(16384u) : "memory");
        asm volatile("cp.async.bulk.commit_group;" ::: "memory");
        asm volatile("cp.async.bulk.wait_group 0;" ::: "memory");
    }
}

extern "C" void kernel_launch(void* const* d_in, const int* in_sizes, int n_in,
                              void* d_out, int out_size) {
    const float4* in  = (const float4*)d_in[0];
    float4*       out = (float4*)d_out;

    reshape_78271484002964_kernel<<<NBLOCKS, 256>>>(in, out);
}

// round 11
// speedup vs baseline: 1.1380x; 1.1380x over previous
#include <cuda_runtime.h>

// Permutation: x[B=16, C=64, H=256, W=256] fp32
//   out[b][i][j][k][cc][hh][ww] = x[b][i*32+cc][j*16+hh][k*16+ww]
//
// Round 11: R6 structure, but each CTA processes TWO consecutive j-tiles with
// a single 17KB smem buffer. Tile-1's loads are issued right after the first
// barrier, overlapping tile-0's output phase (latency hidden, smem footprint
// unchanged -> high residency, 32KB read run per CTA).
// SMEM rows padded 64->68 f4: conflict-free 128-bit STS and LDS.

static constexpr unsigned NBLOCKS = 16u * 2u * 32u * 8u;  // (b,i,cc,jp) = 8192

__device__ __forceinline__ void emit_tile(const float4* __restrict__ sm,
                                          float4* __restrict__ out,
                                          unsigned out_base, unsigned t) {
    // out f4 idx = ww4 | hh<<2 | cc<<6 | k<<11 | j<<15 | i<<19 | b<<20
#pragma unroll
    for (unsigned it = 0; it < 4u; ++it) {
        unsigned p   = t + it * 256u;        // output-linear offset in tile
        unsigned ww4 = p & 3u;
        unsigned hh  = (p >> 2) & 15u;
        unsigned k   = p >> 6;
        float4 v = sm[hh * 68u + (k << 2) + ww4];
        __stcs(&out[out_base + (k << 11) + (p & 63u)], v);
    }
}

__global__ __launch_bounds__(256)
void reshape_78271484002964_kernel(const float4* __restrict__ in,
                                   float4* __restrict__ out) {
    __shared__ float4 sm[16 * 68];  // 17408 B, single buffer

    unsigned bid = blockIdx.x;
    unsigned jp = bid & 7u;            // j-pair: j = 2*jp, 2*jp+1
    unsigned cc = (bid >> 3) & 31u;
    unsigned i  = (bid >> 8) & 1u;
    unsigned b  = bid >> 9;

    unsigned channel = (b << 6) + (i << 5) + cc;
    const float4* src = in + (channel << 14) + (jp << 11);  // 2 j-blocks = 2048 f4

    unsigned t = threadIdx.x;

    // Fixed smem write addresses (input-linear -> padded rows).
    unsigned sa0 = ((t        ) >> 6) * 68u + ((t        ) & 63u);
    unsigned sa1 = ((t + 256u ) >> 6) * 68u + ((t + 256u ) & 63u);
    unsigned sa2 = ((t + 512u ) >> 6) * 68u + ((t + 512u ) & 63u);
    unsigned sa3 = ((t + 768u ) >> 6) * 68u + ((t + 768u ) & 63u);

    unsigned ob0 = (cc << 6) + ((jp << 1) << 15) + (i << 19) + (b << 20);

    // ---- Tile 0: load + stage ----
    {
        float4 v0 = __ldcs(src + t);
        float4 v1 = __ldcs(src + t + 256u);
        float4 v2 = __ldcs(src + t + 512u);
        float4 v3 = __ldcs(src + t + 768u);
        sm[sa0] = v0; sm[sa1] = v1; sm[sa2] = v2; sm[sa3] = v3;
    }
    __syncthreads();

    // ---- Tile 1: issue loads NOW (fly during tile-0 output phase) ----
    float4 w0 = __ldcs(src + t + 1024u);
    float4 w1 = __ldcs(src + t + 1280u);
    float4 w2 = __ldcs(src + t + 1536u);
    float4 w3 = __ldcs(src + t + 1792u);

    // ---- Tile 0: output phase ----
    emit_tile(sm, out, ob0, t);

    __syncthreads();  // all tile-0 reads done before overwrite

    // ---- Tile 1: stage + output ----
    sm[sa0] = w0; sm[sa1] = w1; sm[sa2] = w2; sm[sa3] = w3;
    __syncthreads();

    emit_tile(sm, out, ob0 + (1u << 15), t);
}

extern "C" void kernel_launch(void* const* d_in, const int* in_sizes, int n_in,
                              void* d_out, int out_size) {
    const float4* in  = (const float4*)d_in[0];
    float4*       out = (float4*)d_out;

    reshape_78271484002964_kernel<<<NBLOCKS, 256>>>(in, out);
}